// round 16
// baseline (speedup 1.0000x reference)
#include <cuda_runtime.h>
#include <cuda_fp16.h>
#include <cstdint>

#define D 64
#define NCAP 160000
#define ECAP 4200000
#define GK 64             // plain fp16 GEMM operands
#define APCAP (4096 * GK)
#define BPCAP (51200 * GK)

// Scratch (allocation-free rule: __device__ globals).
__device__ __half g_xh[NCAP * D];
__device__ __half g_yh[NCAP * D];
__device__ float  g_acc[NCAP * D];
__device__ int    g_cnt[NCAP];
__device__ int    g_off[NCAP];
__device__ int    g_cur[NCAP];
__device__ int2   g_rowinfo[NCAP];    // {start, deg}
__device__ int    g_bsum[1024];
__device__ int2   g_epack[ECAP];
__device__ __half g_Ap[APCAP];
__device__ __half g_Bp[BPCAP];

// ---------------------------------------------------------------------------
// init: acc = concat(ue, ie) fp32; xh = fp16; zeroes cnt (fused).
// ---------------------------------------------------------------------------
__global__ void init_kernel(const float* __restrict__ ue, const float* __restrict__ ie,
                            __half* __restrict__ xh, float* __restrict__ acc,
                            int* __restrict__ cnt, int n_nodes,
                            int nu_elems, int total_elems) {
    int tid = blockIdx.x * blockDim.x + threadIdx.x;
    if (tid < n_nodes) cnt[tid] = 0;
    int i = tid * 4;
    if (i >= total_elems) return;
    float4 v = (i < nu_elems) ? *(const float4*)(ue + i)
                              : *(const float4*)(ie + (i - nu_elems));
    *(float4*)(acc + i) = v;
    *(__half2*)(xh + i)     = __floats2half2_rn(v.x, v.y);
    *(__half2*)(xh + i + 2) = __floats2half2_rn(v.z, v.w);
}

// ---------------------------------------------------------------------------
// CSR build (R13-proven)
// ---------------------------------------------------------------------------
__global__ void hist_kernel(const int* __restrict__ ed, int* __restrict__ cnt, int nnz) {
    int e = blockIdx.x * blockDim.x + threadIdx.x;
    if (e < nnz) atomicAdd(&cnt[ed[e]], 1);
}

__device__ __forceinline__ int block_scan_1024(int v, int tid) {
    int lane = tid & 31, w = tid >> 5;
    int s = v;
    #pragma unroll
    for (int o = 1; o < 32; o <<= 1) {
        int t = __shfl_up_sync(0xffffffff, s, o);
        if (lane >= o) s += t;
    }
    __shared__ int wsum[32];
    if (lane == 31) wsum[w] = s;
    __syncthreads();
    if (w == 0) {
        int ws = wsum[lane];
        #pragma unroll
        for (int o = 1; o < 32; o <<= 1) {
            int t = __shfl_up_sync(0xffffffff, ws, o);
            if (lane >= o) ws += t;
        }
        wsum[lane] = ws;
    }
    __syncthreads();
    return s + ((w > 0) ? wsum[w - 1] : 0);
}

__global__ void scan_blocks_kernel(const int* __restrict__ cnt, int* __restrict__ off,
                                   int* __restrict__ bsum, int n) {
    int tid = threadIdx.x;
    int gid = blockIdx.x * 1024 + tid;
    int v = (gid < n) ? cnt[gid] : 0;
    int inc = block_scan_1024(v, tid);
    if (gid < n) off[gid] = inc - v;
    if (tid == 1023) bsum[blockIdx.x] = inc;
}

__global__ void scan_bsum_kernel(int* __restrict__ bsum, int nb) {
    int tid = threadIdx.x;
    int v = (tid < nb) ? bsum[tid] : 0;
    int inc = block_scan_1024(v, tid);
    if (tid < nb) bsum[tid] = inc - v;
}

__global__ void scan_add_kernel(int* __restrict__ off, const int* __restrict__ cnt,
                                int* __restrict__ cur, int2* __restrict__ rowinfo,
                                const int* __restrict__ bsum, int n) {
    int gid = blockIdx.x * blockDim.x + threadIdx.x;
    if (gid < n) {
        int o = off[gid] + bsum[gid >> 10];
        cur[gid] = o;
        rowinfo[gid] = make_int2(o, cnt[gid]);
    }
}

__global__ void scatter_kernel(const float* __restrict__ ev, const int* __restrict__ es,
                               const int* __restrict__ ed, int* __restrict__ cur,
                               int2* __restrict__ epack, int nnz) {
    int e = blockIdx.x * blockDim.x + threadIdx.x;
    if (e < nnz) {
        int d = ed[e];
        int p = atomicAdd(&cur[d], 1);
        epack[p] = make_int2(es[e], __float_as_int(ev[e]));
    }
}

// ---------------------------------------------------------------------------
__device__ __forceinline__ uint32_t smem_u32(const void* p) {
    uint32_t a;
    asm("{ .reg .u64 t; cvta.to.shared.u64 t, %1; cvt.u32.u64 %0, t; }"
        : "=r"(a) : "l"(p));
    return a;
}

// ---------------------------------------------------------------------------
// CSR SPMM v2: cp.async gather staging.
// One warp per node, 8 lanes per edge. Per 32-edge chunk: stage all source
// rows into a private 4KB smem buffer via cp.async (register-free MLP=32,
// ONE scoreboard wait per chunk), then consume via LDS.128.
// Out-of-range quad slots use esv=0/evv=0 (gather row0, add 0) - no guards.
// ---------------------------------------------------------------------------
__global__ void __launch_bounds__(256)
spmm_csr_kernel(const __half* __restrict__ xh, __half* __restrict__ yh,
                float* __restrict__ accb,
                const int2* __restrict__ rowinfo,
                const int2* __restrict__ epack, int n_nodes, int write_y) {
    __shared__ __align__(16) char sbuf[8 * 4096];   // 4KB per warp
    int warp = (blockIdx.x * blockDim.x + threadIdx.x) >> 5;
    int lane = threadIdx.x & 31;
    uint32_t sb = smem_u32(sbuf) + (uint32_t)(threadIdx.x >> 5) * 4096;
    if (warp >= n_nodes) return;

    int2 ri = __ldg(rowinfo + warp);
    int start = ri.x;
    int deg   = ri.y;

    int sub   = lane >> 3;
    uint32_t lo16 = (uint32_t)(lane & 7) * 16;   // byte offset within 128B row
    const char* xb = (const char*)xh;

    float a[8];
    #pragma unroll
    for (int i = 0; i < 8; i++) a[i] = 0.f;

    for (int base = 0; base < deg; base += 32) {
        int m = deg - base;
        if (m > 32) m = 32;
        int   esv = 0;
        float evv = 0.f;
        if (lane < m) {
            int2 md = __ldg(epack + start + base + lane);
            esv = md.x;
            evv = __int_as_float(md.y);
        }
        int iters = (m + 3) >> 2;

        // pass 1: stage gathers (no registers held; MLP = m)
        #pragma unroll 4
        for (int t = 0; t < iters; t++) {
            int idx = t * 4 + sub;
            int s = __shfl_sync(0xffffffff, esv, idx);
            uint32_t dst = sb + (uint32_t)idx * 128 + lo16;
            const char* src = xb + (uint32_t)s * 128 + lo16;
            asm volatile("cp.async.cg.shared.global [%0], [%1], 16;"
                         :: "r"(dst), "l"(src));
        }
        asm volatile("cp.async.commit_group;");
        asm volatile("cp.async.wait_group 0;");
        __syncwarp();

        // pass 2: consume from smem
        #pragma unroll 4
        for (int t = 0; t < iters; t++) {
            int idx = t * 4 + sub;
            float v = __shfl_sync(0xffffffff, evv, idx);
            uint32_t addr = sb + (uint32_t)idx * 128 + lo16;
            uint32_t r0, r1, r2, r3;
            asm volatile("ld.shared.v4.u32 {%0,%1,%2,%3}, [%4];"
                         : "=r"(r0), "=r"(r1), "=r"(r2), "=r"(r3) : "r"(addr));
            uint32_t rr[4] = {r0, r1, r2, r3};
            #pragma unroll
            for (int q = 0; q < 4; q++) {
                float2 f = __half22float2(*(__half2*)&rr[q]);
                a[q * 2 + 0] += v * f.x;
                a[q * 2 + 1] += v * f.y;
            }
        }
        __syncwarp();   // buffer reuse safety for next chunk
    }

    #pragma unroll
    for (int i = 0; i < 8; i++) {
        a[i] += __shfl_down_sync(0xffffffff, a[i], 16);
        a[i] += __shfl_down_sync(0xffffffff, a[i], 8);
    }

    if (lane < 8) {
        uint32_t o = (uint32_t)warp * D + (lane & 7) * 8;
        if (write_y) {
            __half2 hp[4];
            #pragma unroll
            for (int q = 0; q < 4; q++) hp[q] = __floats2half2_rn(a[q * 2], a[q * 2 + 1]);
            *(uint4*)(yh + o) = *(uint4*)hp;
        }
        float4 c0 = *(float4*)(accb + o);
        float4 c1 = *(float4*)(accb + o + 4);
        c0.x += a[0]; c0.y += a[1]; c0.z += a[2]; c0.w += a[3];
        c1.x += a[4]; c1.y += a[5]; c1.z += a[6]; c1.w += a[7];
        *(float4*)(accb + o)     = c0;
        *(float4*)(accb + o + 4) = c1;
    }
}

// ---------------------------------------------------------------------------
// Merged GEMM operand build (plain fp16, K=64). 1/16 scale folded into A.
// ---------------------------------------------------------------------------
__global__ void buildAB_kernel(const float* __restrict__ acc, const int* __restrict__ users,
                               __half* __restrict__ Ap, __half* __restrict__ Bp,
                               int batch, int nu, int ni, int nipad) {
    int idx = blockIdx.x * blockDim.x + threadIdx.x;
    int ta = batch * (D / 2);
    int tb = nipad * (D / 2);
    if (idx < ta) {
        int b = idx / (D / 2), c2 = idx % (D / 2);
        int u = __ldg(users + b);
        float2 v = *(const float2*)(acc + (size_t)u * D + c2 * 2);
        *(__half2*)(Ap + (size_t)b * GK + c2 * 2) =
            __floats2half2_rn(v.x * 0.0625f, v.y * 0.0625f);
    } else if (idx < ta + tb) {
        int k = idx - ta;
        int j = k / (D / 2), c2 = k % (D / 2);
        float2 v = make_float2(0.f, 0.f);
        if (j < ni) v = *(const float2*)(acc + (size_t)(nu + j) * D + c2 * 2);
        *(__half2*)(Bp + (size_t)j * GK + c2 * 2) = __floats2half2_rn(v.x, v.y);
    }
}

// ---------------------------------------------------------------------------
// HMMA fp16 GEMM: 128x128 tile, K=64, B resident for MTILES=4 m-tiles,
// A double-buffered with cp.async prefetch. Direct-store epilogue.
// ---------------------------------------------------------------------------
#define ROWB 144
#define ATILE (128 * ROWB)
#define BOFF (2 * ATILE)
#define GEMM_SMEM_TOT (3 * ATILE)    // 55296
#define MTILES 4
#define KSTEPS 4

__global__ void __launch_bounds__(256, 2)
gemm_mma_kernel(const __half* __restrict__ Ap, const __half* __restrict__ Bp,
                float* __restrict__ out, int batch, int n_items, int mtiles) {
    extern __shared__ char smem[];
    uint32_t sbase = smem_u32(smem);
    int tid = threadIdx.x;
    int wid = tid >> 5;
    int lane = tid & 31;
    int bn = blockIdx.x;
    int bm0 = blockIdx.y * MTILES;

    const char* Bgp = (const char*)(Bp + (size_t)bn * 128 * GK);
    #pragma unroll 4
    for (int i = tid; i < 128 * 8; i += 256) {
        int r = i >> 3, c = i & 7;
        asm volatile("cp.async.cg.shared.global [%0], [%1], 16;"
                     :: "r"(sbase + BOFF + r * ROWB + c * 16), "l"(Bgp + r * 128 + c * 16));
    }
    {
        const char* Agp = (const char*)(Ap + (size_t)bm0 * 128 * GK);
        #pragma unroll 4
        for (int i = tid; i < 128 * 8; i += 256) {
            int r = i >> 3, c = i & 7;
            asm volatile("cp.async.cg.shared.global [%0], [%1], 16;"
                         :: "r"(sbase + r * ROWB + c * 16), "l"(Agp + r * 128 + c * 16));
        }
    }
    asm volatile("cp.async.commit_group;");

    int wm = (wid >> 2) * 64;
    int wn = (wid & 3) * 32;
    uint32_t a_row16 = (wm + (lane & 15)) * ROWB + ((lane & 16) ? 16u : 0u);
    uint32_t b_addr0 = sbase + BOFF + (wn + (lane & 7)) * ROWB + ((lane & 8) ? 16u : 0u);
    int gr = lane >> 2;
    int gc = (lane & 3) * 2;

    for (int mi = 0; mi < MTILES; mi++) {
        int bm = bm0 + mi;
        if (bm >= mtiles) break;

        bool pending = (mi + 1 < MTILES) && (bm + 1 < mtiles);
        if (pending) {
            const char* Agn = (const char*)(Ap + (size_t)(bm + 1) * 128 * GK);
            uint32_t ab = sbase + ((mi + 1) & 1) * ATILE;
            #pragma unroll 4
            for (int i = tid; i < 128 * 8; i += 256) {
                int r = i >> 3, c = i & 7;
                asm volatile("cp.async.cg.shared.global [%0], [%1], 16;"
                             :: "r"(ab + r * ROWB + c * 16), "l"(Agn + r * 128 + c * 16));
            }
            asm volatile("cp.async.commit_group;");
            asm volatile("cp.async.wait_group 1;");
        } else {
            asm volatile("cp.async.wait_group 0;");
        }
        __syncthreads();

        uint32_t abase = sbase + (mi & 1) * ATILE;

        float c[4][4][4];
        #pragma unroll
        for (int mt = 0; mt < 4; mt++)
            #pragma unroll
            for (int nt = 0; nt < 4; nt++)
                #pragma unroll
                for (int q = 0; q < 4; q++) c[mt][nt][q] = 0.f;

        #pragma unroll
        for (int ks = 0; ks < KSTEPS; ks++) {
            uint32_t kb = ks * 32;
            uint32_t a[4][4], b[4][2];
            #pragma unroll
            for (int mt = 0; mt < 4; mt++) {
                uint32_t addr = abase + a_row16 + mt * 16 * ROWB + kb;
                asm volatile("ldmatrix.sync.aligned.m8n8.x4.shared.b16 {%0,%1,%2,%3}, [%4];"
                             : "=r"(a[mt][0]), "=r"(a[mt][1]), "=r"(a[mt][2]), "=r"(a[mt][3])
                             : "r"(addr));
            }
            #pragma unroll
            for (int nt = 0; nt < 4; nt++) {
                uint32_t addr = b_addr0 + nt * 8 * ROWB + kb;
                asm volatile("ldmatrix.sync.aligned.m8n8.x2.shared.b16 {%0,%1}, [%2];"
                             : "=r"(b[nt][0]), "=r"(b[nt][1])
                             : "r"(addr));
            }
            #pragma unroll
            for (int mt = 0; mt < 4; mt++)
                #pragma unroll
                for (int nt = 0; nt < 4; nt++) {
                    asm volatile(
                        "mma.sync.aligned.m16n8k16.row.col.f32.f16.f16.f32 "
                        "{%0,%1,%2,%3}, {%4,%5,%6,%7}, {%8,%9}, {%0,%1,%2,%3};"
                        : "+f"(c[mt][nt][0]), "+f"(c[mt][nt][1]),
                          "+f"(c[mt][nt][2]), "+f"(c[mt][nt][3])
                        : "r"(a[mt][0]), "r"(a[mt][1]), "r"(a[mt][2]), "r"(a[mt][3]),
                          "r"(b[nt][0]), "r"(b[nt][1]));
                }
        }

        #pragma unroll
        for (int mt = 0; mt < 4; mt++) {
            int m0 = bm * 128 + wm + mt * 16 + gr;
            int m1 = m0 + 8;
            #pragma unroll
            for (int nt = 0; nt < 4; nt++) {
                int n = bn * 128 + wn + nt * 8 + gc;
                if (n < n_items) {
                    if (m0 < batch)
                        *(float2*)(out + (size_t)m0 * n_items + n) =
                            make_float2(c[mt][nt][0], c[mt][nt][1]);
                    if (m1 < batch)
                        *(float2*)(out + (size_t)m1 * n_items + n) =
                            make_float2(c[mt][nt][2], c[mt][nt][3]);
                }
            }
        }
        __syncthreads();
    }
}

// ---------------------------------------------------------------------------
extern "C" void kernel_launch(void* const* d_in, const int* in_sizes, int n_in,
                              void* d_out, int out_size) {
    const float* ue    = (const float*)d_in[0];
    const float* ie    = (const float*)d_in[1];
    const float* ev    = (const float*)d_in[2];
    const int*   es    = (const int*)d_in[3];
    const int*   ed    = (const int*)d_in[4];
    const int*   users = (const int*)d_in[5];

    int nu    = in_sizes[0] / D;
    int ni    = in_sizes[1] / D;
    int nnz   = in_sizes[2];
    int batch = in_sizes[5];
    int n_nodes = nu + ni;
    int total = n_nodes * D;
    int nipad = ((ni + 127) / 128) * 128;

    __half *xh, *yh, *Ap, *Bp;
    float *acc;
    int *cnt, *off, *cur, *bsum;
    int2 *epack, *rowinfo;
    cudaGetSymbolAddress((void**)&xh,      g_xh);
    cudaGetSymbolAddress((void**)&yh,      g_yh);
    cudaGetSymbolAddress((void**)&acc,     g_acc);
    cudaGetSymbolAddress((void**)&cnt,     g_cnt);
    cudaGetSymbolAddress((void**)&off,     g_off);
    cudaGetSymbolAddress((void**)&cur,     g_cur);
    cudaGetSymbolAddress((void**)&bsum,    g_bsum);
    cudaGetSymbolAddress((void**)&epack,   g_epack);
    cudaGetSymbolAddress((void**)&rowinfo, g_rowinfo);
    cudaGetSymbolAddress((void**)&Ap,      g_Ap);
    cudaGetSymbolAddress((void**)&Bp,      g_Bp);

    // --- init (cnt zeroing fused) + CSR build ---
    init_kernel<<<(total / 4 + 255) / 256, 256>>>(ue, ie, xh, acc, cnt, n_nodes,
                                                  nu * D, total);
    hist_kernel<<<(nnz + 255) / 256, 256>>>(ed, cnt, nnz);

    int nb = (n_nodes + 1023) / 1024;
    scan_blocks_kernel<<<nb, 1024>>>(cnt, off, bsum, n_nodes);
    scan_bsum_kernel<<<1, 1024>>>(bsum, nb);
    scan_add_kernel<<<(n_nodes + 255) / 256, 256>>>(off, cnt, cur, rowinfo, bsum, n_nodes);
    scatter_kernel<<<(nnz + 255) / 256, 256>>>(ev, es, ed, cur, epack, nnz);

    // --- 3 propagation layers ---
    __half* curx = xh;
    __half* nxt  = yh;
    for (int l = 0; l < 3; l++) {
        long long t = (long long)n_nodes * 32;
        int blocks = (int)((t + 255) / 256);
        spmm_csr_kernel<<<blocks, 256>>>(curx, nxt, acc, rowinfo, epack, n_nodes,
                                         (l < 2) ? 1 : 0);
        __half* tmp = curx; curx = nxt; nxt = tmp;
    }

    // --- merged fp16 operand build (K=64) ---
    {
        int ta = batch * (D / 2);
        int tb = nipad * (D / 2);
        buildAB_kernel<<<(ta + tb + 255) / 256, 256>>>(acc, users, Ap, Bp,
                                                       batch, nu, ni, nipad);
    }

    // --- HMMA fp16 rating GEMM ---
    cudaFuncSetAttribute(gemm_mma_kernel, cudaFuncAttributeMaxDynamicSharedMemorySize,
                         GEMM_SMEM_TOT);
    int mtiles = (batch + 127) / 128;
    dim3 grid(nipad / 128, (mtiles + MTILES - 1) / MTILES);
    gemm_mma_kernel<<<grid, 256, GEMM_SMEM_TOT>>>(Ap, Bp, (float*)d_out, batch, ni, mtiles);
}

// round 17
// speedup vs baseline: 1.2213x; 1.2213x over previous
#include <cuda_runtime.h>
#include <cuda_fp16.h>
#include <cstdint>

#define D 64
#define NCAP 160000
#define ECAP 4200000
#define GK 64             // plain fp16 GEMM operands
#define APCAP (4096 * GK)
#define BPCAP (51200 * GK)

// Scratch (allocation-free rule: __device__ globals).
__device__ __half g_xh[NCAP * D];
__device__ __half g_yh[NCAP * D];
__device__ float  g_acc[NCAP * D];
__device__ int    g_cnt[NCAP];
__device__ int    g_off[NCAP];
__device__ int    g_cur[NCAP];
__device__ int    g_flag[NCAP];       // 1 if node's acc is consumed downstream
__device__ int2   g_rowinfo[NCAP];    // {start, deg | (needed<<31)}
__device__ int    g_bsum[1024];
__device__ int2   g_epack[ECAP];
__device__ __half g_Ap[APCAP];
__device__ __half g_Bp[BPCAP];

// ---------------------------------------------------------------------------
// init: acc = concat(ue, ie) fp32; xh = fp16; zeroes cnt + flag (fused).
// ---------------------------------------------------------------------------
__global__ void init_kernel(const float* __restrict__ ue, const float* __restrict__ ie,
                            __half* __restrict__ xh, float* __restrict__ acc,
                            int* __restrict__ cnt, int* __restrict__ flag, int n_nodes,
                            int nu_elems, int total_elems) {
    int tid = blockIdx.x * blockDim.x + threadIdx.x;
    if (tid < n_nodes) { cnt[tid] = 0; flag[tid] = 0; }
    int i = tid * 4;
    if (i >= total_elems) return;
    float4 v = (i < nu_elems) ? *(const float4*)(ue + i)
                              : *(const float4*)(ie + (i - nu_elems));
    *(float4*)(acc + i) = v;
    *(__half2*)(xh + i)     = __floats2half2_rn(v.x, v.y);
    *(__half2*)(xh + i + 2) = __floats2half2_rn(v.z, v.w);
}

// mark batch users as acc-consumers
__global__ void flag_kernel(const int* __restrict__ users, int* __restrict__ flag,
                            int batch) {
    int i = blockIdx.x * blockDim.x + threadIdx.x;
    if (i < batch) flag[users[i]] = 1;
}

// ---------------------------------------------------------------------------
// CSR build
// ---------------------------------------------------------------------------
__global__ void hist_kernel(const int* __restrict__ ed, int* __restrict__ cnt, int nnz) {
    int e = blockIdx.x * blockDim.x + threadIdx.x;
    if (e < nnz) atomicAdd(&cnt[ed[e]], 1);
}

__device__ __forceinline__ int block_scan_1024(int v, int tid) {
    int lane = tid & 31, w = tid >> 5;
    int s = v;
    #pragma unroll
    for (int o = 1; o < 32; o <<= 1) {
        int t = __shfl_up_sync(0xffffffff, s, o);
        if (lane >= o) s += t;
    }
    __shared__ int wsum[32];
    if (lane == 31) wsum[w] = s;
    __syncthreads();
    if (w == 0) {
        int ws = wsum[lane];
        #pragma unroll
        for (int o = 1; o < 32; o <<= 1) {
            int t = __shfl_up_sync(0xffffffff, ws, o);
            if (lane >= o) ws += t;
        }
        wsum[lane] = ws;
    }
    __syncthreads();
    return s + ((w > 0) ? wsum[w - 1] : 0);
}

__global__ void scan_blocks_kernel(const int* __restrict__ cnt, int* __restrict__ off,
                                   int* __restrict__ bsum, int n) {
    int tid = threadIdx.x;
    int gid = blockIdx.x * 1024 + tid;
    int v = (gid < n) ? cnt[gid] : 0;
    int inc = block_scan_1024(v, tid);
    if (gid < n) off[gid] = inc - v;
    if (tid == 1023) bsum[blockIdx.x] = inc;
}

__global__ void scan_bsum_kernel(int* __restrict__ bsum, int nb) {
    int tid = threadIdx.x;
    int v = (tid < nb) ? bsum[tid] : 0;
    int inc = block_scan_1024(v, tid);
    if (tid < nb) bsum[tid] = inc - v;
}

// builds rowinfo with the "needed" bit: items always, users only if flagged.
__global__ void scan_add_kernel(int* __restrict__ off, const int* __restrict__ cnt,
                                int* __restrict__ cur, int2* __restrict__ rowinfo,
                                const int* __restrict__ bsum,
                                const int* __restrict__ flag, int nu, int n) {
    int gid = blockIdx.x * blockDim.x + threadIdx.x;
    if (gid < n) {
        int o = off[gid] + bsum[gid >> 10];
        cur[gid] = o;
        int needed = (gid >= nu) || flag[gid];
        rowinfo[gid] = make_int2(o, cnt[gid] | (needed << 31));
    }
}

__global__ void scatter_kernel(const float* __restrict__ ev, const int* __restrict__ es,
                               const int* __restrict__ ed, int* __restrict__ cur,
                               int2* __restrict__ epack, int nnz) {
    int e = blockIdx.x * blockDim.x + threadIdx.x;
    if (e < nnz) {
        int d = ed[e];
        int p = atomicAdd(&cur[d], 1);
        epack[p] = make_int2(es[e], __float_as_int(ev[e]));
    }
}

// ---------------------------------------------------------------------------
// CSR SPMM (fp16 storage, fp32 math), one warp per node, 8 lanes per edge.
// R13-proven direct-LDG body. New: acc RMW only for "needed" nodes; on the
// last layer (write_y=0) un-needed nodes exit before doing any work.
// ---------------------------------------------------------------------------
__global__ void __launch_bounds__(256)
spmm_csr_kernel(const __half* __restrict__ xh, __half* __restrict__ yh,
                float* __restrict__ accb,
                const int2* __restrict__ rowinfo,
                const int2* __restrict__ epack, int n_nodes, int write_y) {
    int warp = (blockIdx.x * blockDim.x + threadIdx.x) >> 5;
    int lane = threadIdx.x & 31;
    if (warp >= n_nodes) return;

    int2 ri = __ldg(rowinfo + warp);
    int needed = (ri.y < 0);
    if (!write_y && !needed) return;      // layer-3 dead-node prune
    int start = ri.x;
    int deg   = ri.y & 0x7FFFFFFF;

    int sub  = lane >> 3;
    int col8 = (lane & 7) * 8;

    float a[8];
    #pragma unroll
    for (int i = 0; i < 8; i++) a[i] = 0.f;

    for (int base = 0; base < deg; base += 32) {
        int m = deg - base;
        if (m > 32) m = 32;
        int   esv = 0;
        float evv = 0.f;
        if (lane < m) {
            int2 md = __ldg(epack + start + base + lane);
            esv = md.x;
            evv = __int_as_float(md.y);
        }
        int iters = (m + 3) >> 2;
        #pragma unroll 4
        for (int t = 0; t < iters; t++) {
            int idx = t * 4 + sub;
            float v = __shfl_sync(0xffffffff, evv, idx);
            int   s = __shfl_sync(0xffffffff, esv, idx);
            uint4 raw = *(const uint4*)(xh + (size_t)s * D + col8);
            const __half2* h = (const __half2*)&raw;
            #pragma unroll
            for (int q = 0; q < 4; q++) {
                float2 f = __half22float2(h[q]);
                a[q * 2 + 0] += v * f.x;
                a[q * 2 + 1] += v * f.y;
            }
        }
    }

    #pragma unroll
    for (int i = 0; i < 8; i++) {
        a[i] += __shfl_down_sync(0xffffffff, a[i], 16);
        a[i] += __shfl_down_sync(0xffffffff, a[i], 8);
    }

    if (lane < 8) {
        size_t o = (size_t)warp * D + lane * 8;
        if (write_y) {
            __half2 hp[4];
            #pragma unroll
            for (int q = 0; q < 4; q++) hp[q] = __floats2half2_rn(a[q * 2], a[q * 2 + 1]);
            *(uint4*)(yh + o) = *(uint4*)hp;
        }
        if (needed) {
            float4 c0 = *(float4*)(accb + o);
            float4 c1 = *(float4*)(accb + o + 4);
            c0.x += a[0]; c0.y += a[1]; c0.z += a[2]; c0.w += a[3];
            c1.x += a[4]; c1.y += a[5]; c1.z += a[6]; c1.w += a[7];
            *(float4*)(accb + o)     = c0;
            *(float4*)(accb + o + 4) = c1;
        }
    }
}

// ---------------------------------------------------------------------------
// Merged GEMM operand build (plain fp16, K=64). 1/16 scale folded into A.
// ---------------------------------------------------------------------------
__global__ void buildAB_kernel(const float* __restrict__ acc, const int* __restrict__ users,
                               __half* __restrict__ Ap, __half* __restrict__ Bp,
                               int batch, int nu, int ni, int nipad) {
    int idx = blockIdx.x * blockDim.x + threadIdx.x;
    int ta = batch * (D / 2);
    int tb = nipad * (D / 2);
    if (idx < ta) {
        int b = idx / (D / 2), c2 = idx % (D / 2);
        int u = __ldg(users + b);
        float2 v = *(const float2*)(acc + (size_t)u * D + c2 * 2);
        *(__half2*)(Ap + (size_t)b * GK + c2 * 2) =
            __floats2half2_rn(v.x * 0.0625f, v.y * 0.0625f);
    } else if (idx < ta + tb) {
        int k = idx - ta;
        int j = k / (D / 2), c2 = k % (D / 2);
        float2 v = make_float2(0.f, 0.f);
        if (j < ni) v = *(const float2*)(acc + (size_t)(nu + j) * D + c2 * 2);
        *(__half2*)(Bp + (size_t)j * GK + c2 * 2) = __floats2half2_rn(v.x, v.y);
    }
}

// ---------------------------------------------------------------------------
// HMMA fp16 GEMM: 128x128 tile, K=64, B resident for MTILES=4 m-tiles,
// A double-buffered with cp.async prefetch. Direct-store epilogue.
// ---------------------------------------------------------------------------
#define ROWB 144
#define ATILE (128 * ROWB)
#define BOFF (2 * ATILE)
#define GEMM_SMEM_TOT (3 * ATILE)    // 55296
#define MTILES 4
#define KSTEPS 4

__device__ __forceinline__ uint32_t smem_u32(const void* p) {
    uint32_t a;
    asm("{ .reg .u64 t; cvta.to.shared.u64 t, %1; cvt.u32.u64 %0, t; }"
        : "=r"(a) : "l"(p));
    return a;
}

__global__ void __launch_bounds__(256, 2)
gemm_mma_kernel(const __half* __restrict__ Ap, const __half* __restrict__ Bp,
                float* __restrict__ out, int batch, int n_items, int mtiles) {
    extern __shared__ char smem[];
    uint32_t sbase = smem_u32(smem);
    int tid = threadIdx.x;
    int wid = tid >> 5;
    int lane = tid & 31;
    int bn = blockIdx.x;
    int bm0 = blockIdx.y * MTILES;

    const char* Bgp = (const char*)(Bp + (size_t)bn * 128 * GK);
    #pragma unroll 4
    for (int i = tid; i < 128 * 8; i += 256) {
        int r = i >> 3, c = i & 7;
        asm volatile("cp.async.cg.shared.global [%0], [%1], 16;"
                     :: "r"(sbase + BOFF + r * ROWB + c * 16), "l"(Bgp + r * 128 + c * 16));
    }
    {
        const char* Agp = (const char*)(Ap + (size_t)bm0 * 128 * GK);
        #pragma unroll 4
        for (int i = tid; i < 128 * 8; i += 256) {
            int r = i >> 3, c = i & 7;
            asm volatile("cp.async.cg.shared.global [%0], [%1], 16;"
                         :: "r"(sbase + r * ROWB + c * 16), "l"(Agp + r * 128 + c * 16));
        }
    }
    asm volatile("cp.async.commit_group;");

    int wm = (wid >> 2) * 64;
    int wn = (wid & 3) * 32;
    uint32_t a_row16 = (wm + (lane & 15)) * ROWB + ((lane & 16) ? 16u : 0u);
    uint32_t b_addr0 = sbase + BOFF + (wn + (lane & 7)) * ROWB + ((lane & 8) ? 16u : 0u);
    int gr = lane >> 2;
    int gc = (lane & 3) * 2;

    for (int mi = 0; mi < MTILES; mi++) {
        int bm = bm0 + mi;
        if (bm >= mtiles) break;

        bool pending = (mi + 1 < MTILES) && (bm + 1 < mtiles);
        if (pending) {
            const char* Agn = (const char*)(Ap + (size_t)(bm + 1) * 128 * GK);
            uint32_t ab = sbase + ((mi + 1) & 1) * ATILE;
            #pragma unroll 4
            for (int i = tid; i < 128 * 8; i += 256) {
                int r = i >> 3, c = i & 7;
                asm volatile("cp.async.cg.shared.global [%0], [%1], 16;"
                             :: "r"(ab + r * ROWB + c * 16), "l"(Agn + r * 128 + c * 16));
            }
            asm volatile("cp.async.commit_group;");
            asm volatile("cp.async.wait_group 1;");
        } else {
            asm volatile("cp.async.wait_group 0;");
        }
        __syncthreads();

        uint32_t abase = sbase + (mi & 1) * ATILE;

        float c[4][4][4];
        #pragma unroll
        for (int mt = 0; mt < 4; mt++)
            #pragma unroll
            for (int nt = 0; nt < 4; nt++)
                #pragma unroll
                for (int q = 0; q < 4; q++) c[mt][nt][q] = 0.f;

        #pragma unroll
        for (int ks = 0; ks < KSTEPS; ks++) {
            uint32_t kb = ks * 32;
            uint32_t a[4][4], b[4][2];
            #pragma unroll
            for (int mt = 0; mt < 4; mt++) {
                uint32_t addr = abase + a_row16 + mt * 16 * ROWB + kb;
                asm volatile("ldmatrix.sync.aligned.m8n8.x4.shared.b16 {%0,%1,%2,%3}, [%4];"
                             : "=r"(a[mt][0]), "=r"(a[mt][1]), "=r"(a[mt][2]), "=r"(a[mt][3])
                             : "r"(addr));
            }
            #pragma unroll
            for (int nt = 0; nt < 4; nt++) {
                uint32_t addr = b_addr0 + nt * 8 * ROWB + kb;
                asm volatile("ldmatrix.sync.aligned.m8n8.x2.shared.b16 {%0,%1}, [%2];"
                             : "=r"(b[nt][0]), "=r"(b[nt][1])
                             : "r"(addr));
            }
            #pragma unroll
            for (int mt = 0; mt < 4; mt++)
                #pragma unroll
                for (int nt = 0; nt < 4; nt++) {
                    asm volatile(
                        "mma.sync.aligned.m16n8k16.row.col.f32.f16.f16.f32 "
                        "{%0,%1,%2,%3}, {%4,%5,%6,%7}, {%8,%9}, {%0,%1,%2,%3};"
                        : "+f"(c[mt][nt][0]), "+f"(c[mt][nt][1]),
                          "+f"(c[mt][nt][2]), "+f"(c[mt][nt][3])
                        : "r"(a[mt][0]), "r"(a[mt][1]), "r"(a[mt][2]), "r"(a[mt][3]),
                          "r"(b[nt][0]), "r"(b[nt][1]));
                }
        }

        #pragma unroll
        for (int mt = 0; mt < 4; mt++) {
            int m0 = bm * 128 + wm + mt * 16 + gr;
            int m1 = m0 + 8;
            #pragma unroll
            for (int nt = 0; nt < 4; nt++) {
                int n = bn * 128 + wn + nt * 8 + gc;
                if (n < n_items) {
                    if (m0 < batch)
                        *(float2*)(out + (size_t)m0 * n_items + n) =
                            make_float2(c[mt][nt][0], c[mt][nt][1]);
                    if (m1 < batch)
                        *(float2*)(out + (size_t)m1 * n_items + n) =
                            make_float2(c[mt][nt][2], c[mt][nt][3]);
                }
            }
        }
        __syncthreads();
    }
}

// ---------------------------------------------------------------------------
extern "C" void kernel_launch(void* const* d_in, const int* in_sizes, int n_in,
                              void* d_out, int out_size) {
    const float* ue    = (const float*)d_in[0];
    const float* ie    = (const float*)d_in[1];
    const float* ev    = (const float*)d_in[2];
    const int*   es    = (const int*)d_in[3];
    const int*   ed    = (const int*)d_in[4];
    const int*   users = (const int*)d_in[5];

    int nu    = in_sizes[0] / D;
    int ni    = in_sizes[1] / D;
    int nnz   = in_sizes[2];
    int batch = in_sizes[5];
    int n_nodes = nu + ni;
    int total = n_nodes * D;
    int nipad = ((ni + 127) / 128) * 128;

    __half *xh, *yh, *Ap, *Bp;
    float *acc;
    int *cnt, *off, *cur, *bsum, *flag;
    int2 *epack, *rowinfo;
    cudaGetSymbolAddress((void**)&xh,      g_xh);
    cudaGetSymbolAddress((void**)&yh,      g_yh);
    cudaGetSymbolAddress((void**)&acc,     g_acc);
    cudaGetSymbolAddress((void**)&cnt,     g_cnt);
    cudaGetSymbolAddress((void**)&off,     g_off);
    cudaGetSymbolAddress((void**)&cur,     g_cur);
    cudaGetSymbolAddress((void**)&bsum,    g_bsum);
    cudaGetSymbolAddress((void**)&flag,    g_flag);
    cudaGetSymbolAddress((void**)&epack,   g_epack);
    cudaGetSymbolAddress((void**)&rowinfo, g_rowinfo);
    cudaGetSymbolAddress((void**)&Ap,      g_Ap);
    cudaGetSymbolAddress((void**)&Bp,      g_Bp);

    // --- init (cnt+flag zeroing fused) + flags + CSR build ---
    init_kernel<<<(total / 4 + 255) / 256, 256>>>(ue, ie, xh, acc, cnt, flag, n_nodes,
                                                  nu * D, total);
    flag_kernel<<<(batch + 255) / 256, 256>>>(users, flag, batch);
    hist_kernel<<<(nnz + 255) / 256, 256>>>(ed, cnt, nnz);

    int nb = (n_nodes + 1023) / 1024;
    scan_blocks_kernel<<<nb, 1024>>>(cnt, off, bsum, n_nodes);
    scan_bsum_kernel<<<1, 1024>>>(bsum, nb);
    scan_add_kernel<<<(n_nodes + 255) / 256, 256>>>(off, cnt, cur, rowinfo, bsum,
                                                    flag, nu, n_nodes);
    scatter_kernel<<<(nnz + 255) / 256, 256>>>(ev, es, ed, cur, epack, nnz);

    // --- 3 propagation layers (layer 3 prunes dead nodes) ---
    __half* curx = xh;
    __half* nxt  = yh;
    for (int l = 0; l < 3; l++) {
        long long t = (long long)n_nodes * 32;
        int blocks = (int)((t + 255) / 256);
        spmm_csr_kernel<<<blocks, 256>>>(curx, nxt, acc, rowinfo, epack, n_nodes,
                                         (l < 2) ? 1 : 0);
        __half* tmp = curx; curx = nxt; nxt = tmp;
    }

    // --- merged fp16 operand build (K=64) ---
    {
        int ta = batch * (D / 2);
        int tb = nipad * (D / 2);
        buildAB_kernel<<<(ta + tb + 255) / 256, 256>>>(acc, users, Ap, Bp,
                                                       batch, nu, ni, nipad);
    }

    // --- HMMA fp16 rating GEMM ---
    cudaFuncSetAttribute(gemm_mma_kernel, cudaFuncAttributeMaxDynamicSharedMemorySize,
                         GEMM_SMEM_TOT);
    int mtiles = (batch + 127) / 128;
    dim3 grid(nipad / 128, (mtiles + MTILES - 1) / MTILES);
    gemm_mma_kernel<<<grid, 256, GEMM_SMEM_TOT>>>(Ap, Bp, (float*)d_out, batch, ni, mtiles);
}